// round 7
// baseline (speedup 1.0000x reference)
#include <cuda_runtime.h>
#include <cuda_bf16.h>
#include <math.h>
#include <stdint.h>

#define BF16 __nv_bfloat16

// ---------------- scratch ----------------
__device__ BF16  g_Rh[512 * 130 * 352];   // padded R rows, bf16 hi
__device__ BF16  g_Rl[512 * 130 * 352];   // bf16 lo residual
__device__ BF16  g_Wh[3 * 352 * 256];     // W[t][k][f] bf16 hi
__device__ BF16  g_Wl[3 * 352 * 256];     // bf16 lo

static __device__ __forceinline__ uint32_t smem_u32(const void* p) {
    uint32_t r;
    asm("{ .reg .u64 t; cvta.to.shared.u64 t, %1; cvt.u32.u64 %0, t; }" : "=r"(r) : "l"(p));
    return r;
}
static __device__ __forceinline__ void cp16(uint32_t dst, const void* src) {
    asm volatile("cp.async.cg.shared.global [%0], [%1], 16;" :: "r"(dst), "l"(src));
}
static __device__ __forceinline__ void mma_bf16(float* c, const uint32_t* a, uint32_t b0, uint32_t b1) {
    asm volatile(
        "mma.sync.aligned.m16n8k16.row.col.f32.bf16.bf16.f32 "
        "{%0,%1,%2,%3}, {%4,%5,%6,%7}, {%8,%9}, {%0,%1,%2,%3};"
        : "+f"(c[0]), "+f"(c[1]), "+f"(c[2]), "+f"(c[3])
        : "r"(a[0]), "r"(a[1]), "r"(a[2]), "r"(a[3]), "r"(b0), "r"(b1));
}

// ---------------------------------------------------------------------------
// Kernel A: gather, span means, dual softmax, write bf16 hi/lo R (352-wide)
// ---------------------------------------------------------------------------
__global__ void prep_kernel(const int* __restrict__ inputs,
                            const int* __restrict__ e1s_, const int* __restrict__ e1e_,
                            const int* __restrict__ e2s_, const int* __restrict__ e2e_,
                            const int* __restrict__ p1, const int* __restrict__ p2,
                            const float* __restrict__ emb,
                            const float* __restrict__ pos1, const float* __restrict__ pos2)
{
    extern __shared__ float smf[];
    float* we   = smf;                  // [128][101]
    float* emb0 = smf + 12928;
    float* l1   = emb0 + 100;
    float* l2   = l1 + 100;
    float* sc1  = l2 + 100;
    float* sc2  = sc1 + 128;
    float* ine  = sc2 + 128;
    int*   ids  = (int*)(ine + 128);
    int*   q1   = ids + 128;
    int*   q2   = q1 + 128;
    __shared__ float m1s, S1s, m2s, S2s;

    const int b = blockIdx.x;
    const int tid = threadIdx.x;

    if (tid < 128) {
        ids[tid] = inputs[b * 128 + tid];
        q1[tid]  = p1[b * 128 + tid];
        q2[tid]  = p2[b * 128 + tid];
    } else if (tid < 228) {
        emb0[tid - 128] = emb[tid - 128];
    }
    __syncthreads();

    for (int i = tid; i < 128 * 100; i += 256) {
        int l = i / 100, d = i - l * 100;
        we[l * 101 + d] = emb[(long long)ids[l] * 100 + d];
    }
    __syncthreads();

    if (tid < 100) {
        int s1i = e1s_[b], e1i = e1e_[b];
        int s2i = e2s_[b], e2i = e2e_[b];
        float a = 0.f, c = 0.f;
        for (int l = s1i; l <= e1i; ++l) a += we[l * 101 + tid];
        for (int l = s2i; l <= e2i; ++l) c += we[l * 101 + tid];
        l1[tid] = a / (float)(e1i - s1i + 1);
        l2[tid] = c / (float)(e2i - s2i + 1);
    }
    __syncthreads();

    if (tid < 128) {
        float a = 0.f, c = 0.f;
        const float* w = we + tid * 101;
        #pragma unroll 4
        for (int d = 0; d < 100; ++d) { a += w[d] * l1[d]; c += w[d] * l2[d]; }
        sc1[tid] = a; sc2[tid] = c;
    }
    __syncthreads();

    if (tid < 64) {
        const float* sc = (tid < 32) ? sc1 : sc2;
        int lane = tid & 31;
        float m = -1e30f;
        for (int l = lane; l < 128; l += 32) m = fmaxf(m, sc[l]);
        for (int o = 16; o; o >>= 1) m = fmaxf(m, __shfl_xor_sync(0xffffffffu, m, o));
        float s = 0.f;
        for (int l = lane; l < 128; l += 32) s += expf(sc[l] - m);
        for (int o = 16; o; o >>= 1) s += __shfl_xor_sync(0xffffffffu, s, o);
        if (lane == 0) {
            if (tid < 32) { m1s = m; S1s = s; } else { m2s = m; S2s = s; }
        }
    }
    __syncthreads();

    if (tid < 128)
        ine[tid] = 0.5f * (expf(sc1[tid] - m1s) / S1s + expf(sc2[tid] - m2s) / S2s);
    __syncthreads();

    BF16* rh = g_Rh + ((size_t)b * 130 + 1) * 352;
    BF16* rl = g_Rl + ((size_t)b * 130 + 1) * 352;
    for (int i = tid; i < 128 * 352; i += 256) {
        int l = i / 352, d = i - l * 352;
        float v = 0.f;
        if (d < 350) {
            float s = ine[l];
            if (d < 300) {
                if (l != 0) {
                    int j = d / 100, dd = d - j * 100;
                    int lw = l - 1 + j;
                    v = ((lw < 128) ? we[lw * 101 + dd] : emb0[dd]) * s;
                }
            } else if (d < 325) {
                v = pos1[q1[l] * 25 + (d - 300)] * s;
            } else {
                v = pos2[q2[l] * 25 + (d - 325)] * s;
            }
        }
        BF16 hi = __float2bfloat16(v);
        BF16 lo = __float2bfloat16(v - __bfloat162float(hi));
        rh[(size_t)l * 352 + d] = hi;
        rl[(size_t)l * 352 + d] = lo;
    }
    for (int d = tid; d < 352; d += 256) {
        BF16 z = __float2bfloat16(0.f);
        g_Rh[((size_t)b * 130) * 352 + d] = z;
        g_Rh[((size_t)b * 130 + 129) * 352 + d] = z;
        g_Rl[((size_t)b * 130) * 352 + d] = z;
        g_Rl[((size_t)b * 130 + 129) * 352 + d] = z;
    }
}

// ---------------------------------------------------------------------------
// Kernel W: split conv weights -> [t][k(352)][f(256)] bf16 hi/lo
// ---------------------------------------------------------------------------
__global__ void wsplit_kernel(const float* __restrict__ convw)
{
    int kk = blockIdx.x;      // 0..1055 = t*352 + k
    int f  = threadIdx.x;     // 0..255
    int t  = kk / 352;
    int k  = kk - t * 352;
    float v = (k < 350) ? convw[(size_t)f * 1050 + t * 350 + k] : 0.f;
    BF16 hi = __float2bfloat16(v);
    BF16 lo = __float2bfloat16(v - __bfloat162float(hi));
    g_Wh[(size_t)kk * 256 + f] = hi;
    g_Wl[(size_t)kk * 256 + f] = lo;
}

// ---------------------------------------------------------------------------
// Kernel B (fused): conv bf16x3 tensor GEMM + bias + tanh + T=Rc.U +
// G=T.WL + softmax over l + maxpool -> out. One CTA per batch b.
// 512 thr = 16 warps (4m x 4n), warp tile 32x64, 33 chunks of k=32,
// 3-stage cp.async pipeline.
// smem: 3 buffers x 54272 = 162816 B; epilogue reuses:
//   Rc_s [128][260] f32 @0 (133120), Us @133120 (19456), Ts @152576 (10240)
// ---------------------------------------------------------------------------
#define ABUF 54272
#define AH_OFF 0
#define AL_OFF 10240
#define BH_OFF 20480
#define BL_OFF 37376
#define CONV_SMEM (3 * ABUF)

static __device__ __forceinline__ void conv_load(uint32_t smb, int q, int bufi, int b, int tid)
{
    const int t = q / 11, kc = q - t * 11;
    const uint32_t d = smb + bufi * ABUF;
    {
        int am = tid >> 2, ac = (tid & 3) * 8;
        size_t src = ((size_t)(b * 130 + t + am)) * 352 + kc * 32 + ac;
        uint32_t dst = d + am * 80 + ac * 2;
        cp16(dst + AH_OFF, g_Rh + src);
        cp16(dst + AL_OFF, g_Rl + src);
    }
    {
        int bk = tid >> 4, bn = (tid & 15) * 16;
        size_t src = ((size_t)(t * 352 + kc * 32 + bk)) * 256 + bn;
        uint32_t dst = d + bk * 528 + bn * 2;
        cp16(dst + BH_OFF,      g_Wh + src);
        cp16(dst + BH_OFF + 16, g_Wh + src + 8);
        cp16(dst + BL_OFF,      g_Wl + src);
        cp16(dst + BL_OFF + 16, g_Wl + src + 8);
    }
}

__global__ __launch_bounds__(512, 1) void conv_fused_kernel(const float* __restrict__ convb,
                                                            const float* __restrict__ U,
                                                            const float* __restrict__ WL,
                                                            float* __restrict__ out)
{
    extern __shared__ __align__(256) char smc[];
    const uint32_t smb = smem_u32(smc);
    const int tid = threadIdx.x;
    const int lane = tid & 31;
    const int wid  = tid >> 5;
    const int wm = wid & 3;           // m 0..3
    const int wn = wid >> 2;          // n 0..3
    const int b  = blockIdx.x;

    float acc[2][8][4];
    #pragma unroll
    for (int s = 0; s < 2; ++s)
        #pragma unroll
        for (int j = 0; j < 8; ++j)
            #pragma unroll
            for (int x = 0; x < 4; ++x) acc[s][j][x] = 0.f;

    conv_load(smb, 0, 0, b, tid);
    asm volatile("cp.async.commit_group;" ::: "memory");
    conv_load(smb, 1, 1, b, tid);
    asm volatile("cp.async.commit_group;" ::: "memory");

    const uint32_t aAddrBase = smb + (wm * 32 + (lane & 15)) * 80 + (lane >> 4) * 16;
    const uint32_t bAddrBase = smb + ((lane & 7) + ((lane >> 3) & 1) * 8) * 528
                                   + (wn * 64 + (lane >> 4) * 8) * 2;

    int bufi = 0;
    for (int q = 0; q < 33; ++q) {
        if (q < 31) asm volatile("cp.async.wait_group 1;" ::: "memory");
        else        asm volatile("cp.async.wait_group 0;" ::: "memory");
        __syncthreads();
        if (q + 2 < 33) {
            int nb = bufi + 2; if (nb >= 3) nb -= 3;
            conv_load(smb, q + 2, nb, b, tid);
            asm volatile("cp.async.commit_group;" ::: "memory");
        }
        const uint32_t d = bufi * ABUF;

        #pragma unroll
        for (int ks = 0; ks < 2; ++ks) {
            uint32_t ah[2][4], al[2][4];
            #pragma unroll
            for (int s = 0; s < 2; ++s) {
                uint32_t addr = aAddrBase + d + (s * 16) * 80 + ks * 32;
                asm volatile("ldmatrix.sync.aligned.m8n8.x4.shared.b16 {%0,%1,%2,%3}, [%4];"
                             : "=r"(ah[s][0]), "=r"(ah[s][1]), "=r"(ah[s][2]), "=r"(ah[s][3])
                             : "r"(addr + AH_OFF));
                asm volatile("ldmatrix.sync.aligned.m8n8.x4.shared.b16 {%0,%1,%2,%3}, [%4];"
                             : "=r"(al[s][0]), "=r"(al[s][1]), "=r"(al[s][2]), "=r"(al[s][3])
                             : "r"(addr + AL_OFF));
            }
            #pragma unroll
            for (int i = 0; i < 4; ++i) {
                uint32_t bb[4];
                uint32_t addr = bAddrBase + d + (ks * 16) * 528 + i * 32;
                asm volatile("ldmatrix.sync.aligned.m8n8.x4.trans.shared.b16 {%0,%1,%2,%3}, [%4];"
                             : "=r"(bb[0]), "=r"(bb[1]), "=r"(bb[2]), "=r"(bb[3])
                             : "r"(addr + BH_OFF));
                #pragma unroll
                for (int s = 0; s < 2; ++s) {
                    mma_bf16(acc[s][2 * i],     ah[s], bb[0], bb[1]);
                    mma_bf16(acc[s][2 * i + 1], ah[s], bb[2], bb[3]);
                    mma_bf16(acc[s][2 * i],     al[s], bb[0], bb[1]);
                    mma_bf16(acc[s][2 * i + 1], al[s], bb[2], bb[3]);
                }
                asm volatile("ldmatrix.sync.aligned.m8n8.x4.trans.shared.b16 {%0,%1,%2,%3}, [%4];"
                             : "=r"(bb[0]), "=r"(bb[1]), "=r"(bb[2]), "=r"(bb[3])
                             : "r"(addr + BL_OFF));
                #pragma unroll
                for (int s = 0; s < 2; ++s) {
                    mma_bf16(acc[s][2 * i],     ah[s], bb[0], bb[1]);
                    mma_bf16(acc[s][2 * i + 1], ah[s], bb[2], bb[3]);
                }
            }
        }
        if (++bufi >= 3) bufi -= 3;
        __syncthreads();   // all warps done with this buffer before reuse
    }

    // ---------------- fused epilogue ----------------
    float* Rc_s = (float*)smc;                 // [128][260]
    float* Us   = (float*)(smc + 133120);      // [256*19]
    float* Ts   = (float*)(smc + 152576);      // [128][20]
    float* Pm   = Us;                          // partial combine reuse (after T)
    float* Ps   = Us + 256;
    float* Pv   = Us + 512;

    // bias + tanh -> Rc_s
    const int col_base = wn * 64 + (lane & 3) * 2;
    #pragma unroll
    for (int s = 0; s < 2; ++s) {
        int row = wm * 32 + s * 16 + (lane >> 2);
        #pragma unroll
        for (int j = 0; j < 8; ++j) {
            int col = col_base + j * 8;
            float b0 = __ldg(convb + col), b1 = __ldg(convb + col + 1);
            Rc_s[row * 260 + col]           = tanhf(acc[s][j][0] + b0);
            Rc_s[row * 260 + col + 1]       = tanhf(acc[s][j][1] + b1);
            Rc_s[(row + 8) * 260 + col]     = tanhf(acc[s][j][2] + b0);
            Rc_s[(row + 8) * 260 + col + 1] = tanhf(acc[s][j][3] + b1);
        }
    }
    // U -> smem
    for (int i = tid; i < 4864; i += 512) Us[i] = U[i];
    __syncthreads();

    // T[l][c] = sum_f Rc_s[l][f] * U[f][c]; warp w handles rows w*8..w*8+7
    #pragma unroll 1
    for (int r = 0; r < 8; ++r) {
        const int l = wid * 8 + r;
        const float* rcl = Rc_s + l * 260;
        float tac[19];
        #pragma unroll
        for (int c = 0; c < 19; ++c) tac[c] = 0.f;
        #pragma unroll
        for (int i = 0; i < 8; ++i) {
            int f = i * 32 + lane;
            float a = rcl[f];
            const float* up = Us + f * 19;
            #pragma unroll
            for (int c = 0; c < 19; ++c) tac[c] += a * up[c];
        }
        #pragma unroll
        for (int c = 0; c < 19; ++c) {
            float v = tac[c];
            #pragma unroll
            for (int o = 16; o; o >>= 1) v += __shfl_xor_sync(0xffffffffu, v, o);
            if (lane == c) Ts[l * 20 + c] = v;
        }
    }
    __syncthreads();

    // head: G[l][g] = sum_c T[l][c]*WL[c][g]; softmax over l; out = max_l Rc*softG
    const int g = tid & 255;
    const int half = tid >> 8;          // 0: l in [0,64), 1: [64,128)
    float wl[19];
    #pragma unroll
    for (int c = 0; c < 19; ++c) wl[c] = __ldg(WL + c * 256 + g);

    const int l0 = half * 64;
    float m, S, vmax;
    {
        const float* tl = Ts + l0 * 20;
        float gg = 0.f;
        #pragma unroll
        for (int c = 0; c < 19; ++c) gg += tl[c] * wl[c];
        m = gg; S = 1.f; vmax = Rc_s[l0 * 260 + g];
    }
    for (int l = l0 + 1; l < l0 + 64; ++l) {
        const float* tl = Ts + l * 20;
        float gg = 0.f;
        #pragma unroll
        for (int c = 0; c < 19; ++c) gg += tl[c] * wl[c];
        float rc = Rc_s[l * 260 + g];
        float m2 = fmaxf(m, gg);
        float c1 = __expf(m - m2), c2 = __expf(gg - m2);
        S = S * c1 + c2;
        vmax = fmaxf(vmax * c1, rc * c2);
        m = m2;
    }
    __syncthreads();     // Ts reads done before Pm/Ps/Pv overwrite Us region
    if (half == 1) { Pm[g] = m; Ps[g] = S; Pv[g] = vmax; }
    __syncthreads();
    if (half == 0) {
        float m2 = Pm[g], S2 = Ps[g], v2 = Pv[g];
        float M = fmaxf(m, m2);
        float c1 = __expf(m - M), c2 = __expf(m2 - M);
        float Sc = S * c1 + S2 * c2;
        float V  = fmaxf(vmax * c1, v2 * c2);
        out[(size_t)b * 256 + g] = V / Sc;
    }
}

__global__ void wl_copy_kernel(const float* __restrict__ WL, float* __restrict__ out)
{
    int i = blockIdx.x * 256 + threadIdx.x;
    if (i < 19 * 256) out[512 * 256 + i] = WL[i];
}

// ---------------------------------------------------------------------------
extern "C" void kernel_launch(void* const* d_in, const int* in_sizes, int n_in,
                              void* d_out, int out_size)
{
    const int*   inputs = (const int*)d_in[0];
    const int*   e1s    = (const int*)d_in[1];
    const int*   e1e    = (const int*)d_in[2];
    const int*   e2s    = (const int*)d_in[3];
    const int*   e2e    = (const int*)d_in[4];
    const int*   p1     = (const int*)d_in[5];
    const int*   p2     = (const int*)d_in[6];
    const float* emb    = (const float*)d_in[7];
    const float* pos1   = (const float*)d_in[8];
    const float* pos2   = (const float*)d_in[9];
    const float* convw  = (const float*)d_in[10];
    const float* convb  = (const float*)d_in[11];
    const float* U      = (const float*)d_in[12];
    const float* WL     = (const float*)d_in[13];
    float* out = (float*)d_out;

    const int PREP_SMEM = 13996 * 4;
    cudaFuncSetAttribute(prep_kernel, cudaFuncAttributeMaxDynamicSharedMemorySize, PREP_SMEM);
    cudaFuncSetAttribute(conv_fused_kernel, cudaFuncAttributeMaxDynamicSharedMemorySize, CONV_SMEM);

    prep_kernel<<<512, 256, PREP_SMEM>>>(inputs, e1s, e1e, e2s, e2e, p1, p2, emb, pos1, pos2);
    wsplit_kernel<<<1056, 256>>>(convw);
    conv_fused_kernel<<<512, 512, CONV_SMEM>>>(convb, U, WL, out);
    wl_copy_kernel<<<19, 256>>>(WL, out);
}

// round 8
// speedup vs baseline: 1.1465x; 1.1465x over previous
#include <cuda_runtime.h>
#include <cuda_fp16.h>
#include <math.h>
#include <stdint.h>

#define FP16 __half
#define KPAD 384

// ---------------- scratch ----------------
__device__ FP16  g_Rh[512 * 130 * KPAD];   // padded R rows, fp16 hi
__device__ FP16  g_Rl[512 * 130 * KPAD];   // fp16 lo residual
__device__ FP16  g_Wh[3 * KPAD * 256];     // W[t][k][f] fp16

static __device__ __forceinline__ uint32_t smem_u32(const void* p) {
    uint32_t r;
    asm("{ .reg .u64 t; cvta.to.shared.u64 t, %1; cvt.u32.u64 %0, t; }" : "=r"(r) : "l"(p));
    return r;
}
static __device__ __forceinline__ void cp16(uint32_t dst, const void* src) {
    asm volatile("cp.async.cg.shared.global [%0], [%1], 16;" :: "r"(dst), "l"(src));
}
static __device__ __forceinline__ void mma_fp16(float* c, const uint32_t* a, uint32_t b0, uint32_t b1) {
    asm volatile(
        "mma.sync.aligned.m16n8k16.row.col.f32.f16.f16.f32 "
        "{%0,%1,%2,%3}, {%4,%5,%6,%7}, {%8,%9}, {%0,%1,%2,%3};"
        : "+f"(c[0]), "+f"(c[1]), "+f"(c[2]), "+f"(c[3])
        : "r"(a[0]), "r"(a[1]), "r"(a[2]), "r"(a[3]), "r"(b0), "r"(b1));
}

// ---------------------------------------------------------------------------
// Kernel A: gather, span means, dual softmax, write fp16 hi/lo R (384-wide)
// ---------------------------------------------------------------------------
__global__ void prep_kernel(const int* __restrict__ inputs,
                            const int* __restrict__ e1s_, const int* __restrict__ e1e_,
                            const int* __restrict__ e2s_, const int* __restrict__ e2e_,
                            const int* __restrict__ p1, const int* __restrict__ p2,
                            const float* __restrict__ emb,
                            const float* __restrict__ pos1, const float* __restrict__ pos2)
{
    extern __shared__ float smf[];
    float* we   = smf;                  // [128][101]
    float* emb0 = smf + 12928;
    float* l1   = emb0 + 100;
    float* l2   = l1 + 100;
    float* sc1  = l2 + 100;
    float* sc2  = sc1 + 128;
    float* ine  = sc2 + 128;
    int*   ids  = (int*)(ine + 128);
    int*   q1   = ids + 128;
    int*   q2   = q1 + 128;
    __shared__ float m1s, S1s, m2s, S2s;

    const int b = blockIdx.x;
    const int tid = threadIdx.x;

    if (tid < 128) {
        ids[tid] = inputs[b * 128 + tid];
        q1[tid]  = p1[b * 128 + tid];
        q2[tid]  = p2[b * 128 + tid];
    } else if (tid < 228) {
        emb0[tid - 128] = emb[tid - 128];
    }
    __syncthreads();

    for (int i = tid; i < 128 * 100; i += 256) {
        int l = i / 100, d = i - l * 100;
        we[l * 101 + d] = emb[(long long)ids[l] * 100 + d];
    }
    __syncthreads();

    if (tid < 100) {
        int s1i = e1s_[b], e1i = e1e_[b];
        int s2i = e2s_[b], e2i = e2e_[b];
        float a = 0.f, c = 0.f;
        for (int l = s1i; l <= e1i; ++l) a += we[l * 101 + tid];
        for (int l = s2i; l <= e2i; ++l) c += we[l * 101 + tid];
        l1[tid] = a / (float)(e1i - s1i + 1);
        l2[tid] = c / (float)(e2i - s2i + 1);
    }
    __syncthreads();

    if (tid < 128) {
        float a = 0.f, c = 0.f;
        const float* w = we + tid * 101;
        #pragma unroll 4
        for (int d = 0; d < 100; ++d) { a += w[d] * l1[d]; c += w[d] * l2[d]; }
        sc1[tid] = a; sc2[tid] = c;
    }
    __syncthreads();

    if (tid < 64) {
        const float* sc = (tid < 32) ? sc1 : sc2;
        int lane = tid & 31;
        float m = -1e30f;
        for (int l = lane; l < 128; l += 32) m = fmaxf(m, sc[l]);
        for (int o = 16; o; o >>= 1) m = fmaxf(m, __shfl_xor_sync(0xffffffffu, m, o));
        float s = 0.f;
        for (int l = lane; l < 128; l += 32) s += expf(sc[l] - m);
        for (int o = 16; o; o >>= 1) s += __shfl_xor_sync(0xffffffffu, s, o);
        if (lane == 0) {
            if (tid < 32) { m1s = m; S1s = s; } else { m2s = m; S2s = s; }
        }
    }
    __syncthreads();

    if (tid < 128)
        ine[tid] = 0.5f * (expf(sc1[tid] - m1s) / S1s + expf(sc2[tid] - m2s) / S2s);
    __syncthreads();

    FP16* rh = g_Rh + ((size_t)b * 130 + 1) * KPAD;
    FP16* rl = g_Rl + ((size_t)b * 130 + 1) * KPAD;
    for (int i = tid; i < 128 * KPAD; i += 256) {
        int l = i / KPAD, d = i - l * KPAD;
        float v = 0.f;
        if (d < 350) {
            float s = ine[l];
            if (d < 300) {
                if (l != 0) {
                    int j = d / 100, dd = d - j * 100;
                    int lw = l - 1 + j;
                    v = ((lw < 128) ? we[lw * 101 + dd] : emb0[dd]) * s;
                }
            } else if (d < 325) {
                v = pos1[q1[l] * 25 + (d - 300)] * s;
            } else {
                v = pos2[q2[l] * 25 + (d - 325)] * s;
            }
        }
        FP16 hi = __float2half_rn(v);
        FP16 lo = __float2half_rn(v - __half2float(hi));
        rh[(size_t)l * KPAD + d] = hi;
        rl[(size_t)l * KPAD + d] = lo;
    }
    for (int d = tid; d < KPAD; d += 256) {
        FP16 z = __float2half_rn(0.f);
        g_Rh[((size_t)b * 130) * KPAD + d] = z;
        g_Rh[((size_t)b * 130 + 129) * KPAD + d] = z;
        g_Rl[((size_t)b * 130) * KPAD + d] = z;
        g_Rl[((size_t)b * 130 + 129) * KPAD + d] = z;
    }
}

// ---------------------------------------------------------------------------
// Kernel W: conv weights -> [t][k(384)][f(256)] fp16
// ---------------------------------------------------------------------------
__global__ void wsplit_kernel(const float* __restrict__ convw)
{
    int kk = blockIdx.x;      // 0..1151 = t*384 + k
    int f  = threadIdx.x;     // 0..255
    int t  = kk / KPAD;
    int k  = kk - t * KPAD;
    float v = (k < 350) ? convw[(size_t)f * 1050 + t * 350 + k] : 0.f;
    g_Wh[(size_t)kk * 256 + f] = __float2half_rn(v);
}

// ---------------------------------------------------------------------------
// Kernel B (fused): conv fp16x2 tensor GEMM + bias/tanh + T=Rc.U + head -> out
// One CTA per b. 512 thr = 16 warps (4m x 4n), warp tile 32x64.
// 18 chunks of k=64 (3 taps x 6), passes AhBh + AlBh.
// smem per buf: Ah 128x144B=18432, Al 18432, B 64x528B=33792 -> 70656; x3 bufs.
// Epilogue reuse: Rc_s[128][260] f32 @0, Us @133120, Ts @152576.
// ---------------------------------------------------------------------------
#define BUFSZ 70656
#define A_STR 144
#define B_STR 528
#define AL_OFF 18432
#define B_OFF  36864
#define CONV_SMEM (3 * BUFSZ)   // 211968

static __device__ __forceinline__ void conv_load(uint32_t smb, int q, int bufi, int b, int tid)
{
    const int t = q / 6, kc = q - t * 6;
    const int k0 = kc * 64;
    const uint32_t d = smb + bufi * BUFSZ;
    // A: 128 rows x 64 fp16 (hi+lo): thread row=tid>>2, elems (tid&3)*16..+16
    {
        int am = tid >> 2, ac = (tid & 3) * 16;
        size_t src = ((size_t)(b * 130 + t + am)) * KPAD + k0 + ac;
        uint32_t dst = d + am * A_STR + ac * 2;
        cp16(dst,          g_Rh + src);
        cp16(dst + 16,     g_Rh + src + 8);
        cp16(dst + AL_OFF,      g_Rl + src);
        cp16(dst + AL_OFF + 16, g_Rl + src + 8);
    }
    // B: 64 k-rows x 256 fp16: thread row=tid>>3, elems (tid&7)*32..+32
    {
        int bk = tid >> 3, bn = (tid & 7) * 32;
        size_t src = ((size_t)(t * KPAD + k0 + bk)) * 256 + bn;
        uint32_t dst = d + B_OFF + bk * B_STR + bn * 2;
        cp16(dst,      g_Wh + src);
        cp16(dst + 16, g_Wh + src + 8);
        cp16(dst + 32, g_Wh + src + 16);
        cp16(dst + 48, g_Wh + src + 24);
    }
}

__global__ __launch_bounds__(512, 1) void conv_fused_kernel(const float* __restrict__ convb,
                                                            const float* __restrict__ U,
                                                            const float* __restrict__ WL,
                                                            float* __restrict__ out)
{
    extern __shared__ __align__(256) char smc[];
    const uint32_t smb = smem_u32(smc);
    const int tid = threadIdx.x;
    const int lane = tid & 31;
    const int wid  = tid >> 5;
    const int wm = wid & 3;           // m 0..3
    const int wn = wid >> 2;          // n 0..3
    const int b  = blockIdx.x;

    float acc[2][8][4];
    #pragma unroll
    for (int s = 0; s < 2; ++s)
        #pragma unroll
        for (int j = 0; j < 8; ++j)
            #pragma unroll
            for (int x = 0; x < 4; ++x) acc[s][j][x] = 0.f;

    conv_load(smb, 0, 0, b, tid);
    asm volatile("cp.async.commit_group;" ::: "memory");
    conv_load(smb, 1, 1, b, tid);
    asm volatile("cp.async.commit_group;" ::: "memory");

    const uint32_t aAddrBase = smb + (wm * 32 + (lane & 15)) * A_STR + (lane >> 4) * 16;
    const uint32_t bAddrBase = smb + B_OFF + ((lane & 7) + ((lane >> 3) & 1) * 8) * B_STR
                                   + (wn * 64 + (lane >> 4) * 8) * 2;

    int bufi = 0;
    for (int q = 0; q < 18; ++q) {
        if (q < 16) asm volatile("cp.async.wait_group 1;" ::: "memory");
        else        asm volatile("cp.async.wait_group 0;" ::: "memory");
        __syncthreads();
        if (q + 2 < 18) {
            int nb = bufi + 2; if (nb >= 3) nb -= 3;
            conv_load(smb, q + 2, nb, b, tid);
            asm volatile("cp.async.commit_group;" ::: "memory");
        }
        const uint32_t d = bufi * BUFSZ;

        #pragma unroll
        for (int ks = 0; ks < 4; ++ks) {
            uint32_t ah[2][4], al[2][4];
            #pragma unroll
            for (int s = 0; s < 2; ++s) {
                uint32_t addr = aAddrBase + d + (s * 16) * A_STR + ks * 32;
                asm volatile("ldmatrix.sync.aligned.m8n8.x4.shared.b16 {%0,%1,%2,%3}, [%4];"
                             : "=r"(ah[s][0]), "=r"(ah[s][1]), "=r"(ah[s][2]), "=r"(ah[s][3])
                             : "r"(addr));
                asm volatile("ldmatrix.sync.aligned.m8n8.x4.shared.b16 {%0,%1,%2,%3}, [%4];"
                             : "=r"(al[s][0]), "=r"(al[s][1]), "=r"(al[s][2]), "=r"(al[s][3])
                             : "r"(addr + AL_OFF));
            }
            #pragma unroll
            for (int i = 0; i < 4; ++i) {
                uint32_t bb[4];
                uint32_t addr = bAddrBase + d + (ks * 16) * B_STR + i * 32;
                asm volatile("ldmatrix.sync.aligned.m8n8.x4.trans.shared.b16 {%0,%1,%2,%3}, [%4];"
                             : "=r"(bb[0]), "=r"(bb[1]), "=r"(bb[2]), "=r"(bb[3])
                             : "r"(addr));
                #pragma unroll
                for (int s = 0; s < 2; ++s) {
                    mma_fp16(acc[s][2 * i],     ah[s], bb[0], bb[1]);
                    mma_fp16(acc[s][2 * i + 1], ah[s], bb[2], bb[3]);
                    mma_fp16(acc[s][2 * i],     al[s], bb[0], bb[1]);
                    mma_fp16(acc[s][2 * i + 1], al[s], bb[2], bb[3]);
                }
            }
        }
        if (++bufi >= 3) bufi -= 3;
    }
    __syncthreads();    // mainloop done; buffers become epilogue scratch

    // ---------------- fused epilogue ----------------
    float* Rc_s = (float*)smc;                 // [128][260]
    float* Us   = (float*)(smc + 133120);      // [256*19]
    float* Ts   = (float*)(smc + 152576);      // [128][20]
    float* Pm   = Us;                          // partial combine reuse
    float* Ps   = Us + 256;
    float* Pv   = Us + 512;

    const int col_base = wn * 64 + (lane & 3) * 2;
    #pragma unroll
    for (int s = 0; s < 2; ++s) {
        int row = wm * 32 + s * 16 + (lane >> 2);
        #pragma unroll
        for (int j = 0; j < 8; ++j) {
            int col = col_base + j * 8;
            float b0 = __ldg(convb + col), b1 = __ldg(convb + col + 1);
            Rc_s[row * 260 + col]           = tanhf(acc[s][j][0] + b0);
            Rc_s[row * 260 + col + 1]       = tanhf(acc[s][j][1] + b1);
            Rc_s[(row + 8) * 260 + col]     = tanhf(acc[s][j][2] + b0);
            Rc_s[(row + 8) * 260 + col + 1] = tanhf(acc[s][j][3] + b1);
        }
    }
    for (int i = tid; i < 4864; i += 512) Us[i] = U[i];
    __syncthreads();

    // T[l][c] = sum_f Rc_s[l][f] * U[f][c]; warp w -> rows w*8..+7
    #pragma unroll 1
    for (int r = 0; r < 8; ++r) {
        const int l = wid * 8 + r;
        const float* rcl = Rc_s + l * 260;
        float tac[19];
        #pragma unroll
        for (int c = 0; c < 19; ++c) tac[c] = 0.f;
        #pragma unroll
        for (int i = 0; i < 8; ++i) {
            int f = i * 32 + lane;
            float a = rcl[f];
            const float* up = Us + f * 19;
            #pragma unroll
            for (int c = 0; c < 19; ++c) tac[c] += a * up[c];
        }
        #pragma unroll
        for (int c = 0; c < 19; ++c) {
            float v = tac[c];
            #pragma unroll
            for (int o = 16; o; o >>= 1) v += __shfl_xor_sync(0xffffffffu, v, o);
            if (lane == c) Ts[l * 20 + c] = v;
        }
    }
    __syncthreads();

    // head: per-g online softmax over l + maxpool, split across two halves
    const int g = tid & 255;
    const int half = tid >> 8;
    float wl[19];
    #pragma unroll
    for (int c = 0; c < 19; ++c) wl[c] = __ldg(WL + c * 256 + g);

    const int l0 = half * 64;
    float m, S, vmax;
    {
        const float* tl = Ts + l0 * 20;
        float gg = 0.f;
        #pragma unroll
        for (int c = 0; c < 19; ++c) gg += tl[c] * wl[c];
        m = gg; S = 1.f; vmax = Rc_s[l0 * 260 + g];
    }
    for (int l = l0 + 1; l < l0 + 64; ++l) {
        const float* tl = Ts + l * 20;
        float gg = 0.f;
        #pragma unroll
        for (int c = 0; c < 19; ++c) gg += tl[c] * wl[c];
        float rc = Rc_s[l * 260 + g];
        float m2 = fmaxf(m, gg);
        float c1 = __expf(m - m2), c2 = __expf(gg - m2);
        S = S * c1 + c2;
        vmax = fmaxf(vmax * c1, rc * c2);
        m = m2;
    }
    __syncthreads();
    if (half == 1) { Pm[g] = m; Ps[g] = S; Pv[g] = vmax; }
    __syncthreads();
    if (half == 0) {
        float m2 = Pm[g], S2 = Ps[g], v2 = Pv[g];
        float M = fmaxf(m, m2);
        float c1 = __expf(m - M), c2 = __expf(m2 - M);
        float Sc = S * c1 + S2 * c2;
        float V  = fmaxf(vmax * c1, v2 * c2);
        out[(size_t)b * 256 + g] = V / Sc;
    }
}

__global__ void wl_copy_kernel(const float* __restrict__ WL, float* __restrict__ out)
{
    int i = blockIdx.x * 256 + threadIdx.x;
    if (i < 19 * 256) out[512 * 256 + i] = WL[i];
}

// ---------------------------------------------------------------------------
extern "C" void kernel_launch(void* const* d_in, const int* in_sizes, int n_in,
                              void* d_out, int out_size)
{
    const int*   inputs = (const int*)d_in[0];
    const int*   e1s    = (const int*)d_in[1];
    const int*   e1e    = (const int*)d_in[2];
    const int*   e2s    = (const int*)d_in[3];
    const int*   e2e    = (const int*)d_in[4];
    const int*   p1     = (const int*)d_in[5];
    const int*   p2     = (const int*)d_in[6];
    const float* emb    = (const float*)d_in[7];
    const float* pos1   = (const float*)d_in[8];
    const float* pos2   = (const float*)d_in[9];
    const float* convw  = (const float*)d_in[10];
    const float* convb  = (const float*)d_in[11];
    const float* U      = (const float*)d_in[12];
    const float* WL     = (const float*)d_in[13];
    float* out = (float*)d_out;

    const int PREP_SMEM = 13996 * 4;
    cudaFuncSetAttribute(prep_kernel, cudaFuncAttributeMaxDynamicSharedMemorySize, PREP_SMEM);
    cudaFuncSetAttribute(conv_fused_kernel, cudaFuncAttributeMaxDynamicSharedMemorySize, CONV_SMEM);

    prep_kernel<<<512, 256, PREP_SMEM>>>(inputs, e1s, e1e, e2s, e2e, p1, p2, emb, pos1, pos2);
    wsplit_kernel<<<3 * KPAD, 256>>>(convw);
    conv_fused_kernel<<<512, 512, CONV_SMEM>>>(convb, U, WL, out);
    wl_copy_kernel<<<19, 256>>>(WL, out);
}

// round 9
// speedup vs baseline: 1.4673x; 1.2798x over previous
#include <cuda_runtime.h>
#include <cuda_fp16.h>
#include <math.h>
#include <stdint.h>

#define FP16 __half
#define KPAD 384

// ---------------- scratch ----------------
__device__ FP16  g_Rh[512 * 130 * KPAD];   // padded R rows, fp16
__device__ FP16  g_Wh[3 * KPAD * 256];     // W[t][k][f] fp16

static __device__ __forceinline__ uint32_t smem_u32(const void* p) {
    uint32_t r;
    asm("{ .reg .u64 t; cvta.to.shared.u64 t, %1; cvt.u32.u64 %0, t; }" : "=r"(r) : "l"(p));
    return r;
}
static __device__ __forceinline__ void cp16(uint32_t dst, const void* src) {
    asm volatile("cp.async.cg.shared.global [%0], [%1], 16;" :: "r"(dst), "l"(src));
}
static __device__ __forceinline__ void mma_fp16(float* c, const uint32_t* a, uint32_t b0, uint32_t b1) {
    asm volatile(
        "mma.sync.aligned.m16n8k16.row.col.f32.f16.f16.f32 "
        "{%0,%1,%2,%3}, {%4,%5,%6,%7}, {%8,%9}, {%0,%1,%2,%3};"
        : "+f"(c[0]), "+f"(c[1]), "+f"(c[2]), "+f"(c[3])
        : "r"(a[0]), "r"(a[1]), "r"(a[2]), "r"(a[3]), "r"(b0), "r"(b1));
}

// ---------------------------------------------------------------------------
// Kernel A: gather, span means, dual softmax, write fp16 R (384-wide rows)
// ---------------------------------------------------------------------------
__global__ void prep_kernel(const int* __restrict__ inputs,
                            const int* __restrict__ e1s_, const int* __restrict__ e1e_,
                            const int* __restrict__ e2s_, const int* __restrict__ e2e_,
                            const int* __restrict__ p1, const int* __restrict__ p2,
                            const float* __restrict__ emb,
                            const float* __restrict__ pos1, const float* __restrict__ pos2)
{
    extern __shared__ float smf[];
    float* we   = smf;                  // [128][101]
    float* emb0 = smf + 12928;
    float* l1   = emb0 + 100;
    float* l2   = l1 + 100;
    float* sc1  = l2 + 100;
    float* sc2  = sc1 + 128;
    float* ine  = sc2 + 128;
    int*   ids  = (int*)(ine + 128);
    int*   q1   = ids + 128;
    int*   q2   = q1 + 128;
    __shared__ float m1s, S1s, m2s, S2s;

    const int b = blockIdx.x;
    const int tid = threadIdx.x;

    if (tid < 128) {
        ids[tid] = inputs[b * 128 + tid];
        q1[tid]  = p1[b * 128 + tid];
        q2[tid]  = p2[b * 128 + tid];
    } else if (tid < 228) {
        emb0[tid - 128] = emb[tid - 128];
    }
    __syncthreads();

    for (int i = tid; i < 128 * 100; i += 256) {
        int l = i / 100, d = i - l * 100;
        we[l * 101 + d] = emb[(long long)ids[l] * 100 + d];
    }
    __syncthreads();

    if (tid < 100) {
        int s1i = e1s_[b], e1i = e1e_[b];
        int s2i = e2s_[b], e2i = e2e_[b];
        float a = 0.f, c = 0.f;
        for (int l = s1i; l <= e1i; ++l) a += we[l * 101 + tid];
        for (int l = s2i; l <= e2i; ++l) c += we[l * 101 + tid];
        l1[tid] = a / (float)(e1i - s1i + 1);
        l2[tid] = c / (float)(e2i - s2i + 1);
    }
    __syncthreads();

    if (tid < 128) {
        float a = 0.f, c = 0.f;
        const float* w = we + tid * 101;
        #pragma unroll 4
        for (int d = 0; d < 100; ++d) { a += w[d] * l1[d]; c += w[d] * l2[d]; }
        sc1[tid] = a; sc2[tid] = c;
    }
    __syncthreads();

    if (tid < 64) {
        const float* sc = (tid < 32) ? sc1 : sc2;
        int lane = tid & 31;
        float m = -1e30f;
        for (int l = lane; l < 128; l += 32) m = fmaxf(m, sc[l]);
        for (int o = 16; o; o >>= 1) m = fmaxf(m, __shfl_xor_sync(0xffffffffu, m, o));
        float s = 0.f;
        for (int l = lane; l < 128; l += 32) s += expf(sc[l] - m);
        for (int o = 16; o; o >>= 1) s += __shfl_xor_sync(0xffffffffu, s, o);
        if (lane == 0) {
            if (tid < 32) { m1s = m; S1s = s; } else { m2s = m; S2s = s; }
        }
    }
    __syncthreads();

    if (tid < 128)
        ine[tid] = 0.5f * (expf(sc1[tid] - m1s) / S1s + expf(sc2[tid] - m2s) / S2s);
    __syncthreads();

    FP16* rh = g_Rh + ((size_t)b * 130 + 1) * KPAD;
    for (int i = tid; i < 128 * KPAD; i += 256) {
        int l = i / KPAD, d = i - l * KPAD;
        float v = 0.f;
        if (d < 350) {
            float s = ine[l];
            if (d < 300) {
                if (l != 0) {
                    int j = d / 100, dd = d - j * 100;
                    int lw = l - 1 + j;
                    v = ((lw < 128) ? we[lw * 101 + dd] : emb0[dd]) * s;
                }
            } else if (d < 325) {
                v = pos1[q1[l] * 25 + (d - 300)] * s;
            } else {
                v = pos2[q2[l] * 25 + (d - 325)] * s;
            }
        }
        rh[(size_t)l * KPAD + d] = __float2half_rn(v);
    }
    for (int d = tid; d < KPAD; d += 256) {
        FP16 z = __float2half_rn(0.f);
        g_Rh[((size_t)b * 130) * KPAD + d] = z;
        g_Rh[((size_t)b * 130 + 129) * KPAD + d] = z;
    }
}

// ---------------------------------------------------------------------------
// Kernel W: conv weights -> [t][k(384)][f(256)] fp16
// ---------------------------------------------------------------------------
__global__ void wsplit_kernel(const float* __restrict__ convw)
{
    int kk = blockIdx.x;      // 0..1151 = t*384 + k
    int f  = threadIdx.x;     // 0..255
    int t  = kk / KPAD;
    int k  = kk - t * KPAD;
    float v = (k < 350) ? convw[(size_t)f * 1050 + t * 350 + k] : 0.f;
    g_Wh[(size_t)kk * 256 + f] = __float2half_rn(v);
}

// ---------------------------------------------------------------------------
// Kernel B (fused): conv fp16 tensor GEMM + bias/tanh + T=Rc.U + head -> out
// One CTA per b. 512 thr = 16 warps (4m x 4n), warp tile 32x64.
// 18 chunks of k=64 (3 taps x 6), single fp16 pass.
// smem per buf: A 128x144B=18432, B 64x528B=33792 -> 52224; x3 bufs = 156672.
// Epilogue overlay: Rc_s[128][260] f32 @0 (133120), Us @133120 (19456),
//                   Ts @152576 (10240) -> total 162816 = CONV_SMEM.
// ---------------------------------------------------------------------------
#define BUFSZ 52224
#define A_STR 144
#define B_STR 528
#define B_OFF  18432
#define CONV_SMEM 162816

static __device__ __forceinline__ void conv_load(uint32_t smb, int q, int bufi, int b, int tid)
{
    const int t = q / 6, kc = q - t * 6;
    const int k0 = kc * 64;
    const uint32_t d = smb + bufi * BUFSZ;
    // A: 128 rows x 64 fp16: thread row=tid>>2, elems (tid&3)*16..+16
    {
        int am = tid >> 2, ac = (tid & 3) * 16;
        size_t src = ((size_t)(b * 130 + t + am)) * KPAD + k0 + ac;
        uint32_t dst = d + am * A_STR + ac * 2;
        cp16(dst,      g_Rh + src);
        cp16(dst + 16, g_Rh + src + 8);
    }
    // B: 64 k-rows x 256 fp16: thread row=tid>>3, elems (tid&7)*32..+32
    {
        int bk = tid >> 3, bn = (tid & 7) * 32;
        size_t src = ((size_t)(t * KPAD + k0 + bk)) * 256 + bn;
        uint32_t dst = d + B_OFF + bk * B_STR + bn * 2;
        cp16(dst,      g_Wh + src);
        cp16(dst + 16, g_Wh + src + 8);
        cp16(dst + 32, g_Wh + src + 16);
        cp16(dst + 48, g_Wh + src + 24);
    }
}

__global__ __launch_bounds__(512, 1) void conv_fused_kernel(const float* __restrict__ convb,
                                                            const float* __restrict__ U,
                                                            const float* __restrict__ WL,
                                                            float* __restrict__ out)
{
    extern __shared__ __align__(256) char smc[];
    const uint32_t smb = smem_u32(smc);
    const int tid = threadIdx.x;
    const int lane = tid & 31;
    const int wid  = tid >> 5;
    const int wm = wid & 3;           // m 0..3
    const int wn = wid >> 2;          // n 0..3
    const int b  = blockIdx.x;

    float acc[2][8][4];
    #pragma unroll
    for (int s = 0; s < 2; ++s)
        #pragma unroll
        for (int j = 0; j < 8; ++j)
            #pragma unroll
            for (int x = 0; x < 4; ++x) acc[s][j][x] = 0.f;

    conv_load(smb, 0, 0, b, tid);
    asm volatile("cp.async.commit_group;" ::: "memory");
    conv_load(smb, 1, 1, b, tid);
    asm volatile("cp.async.commit_group;" ::: "memory");

    const uint32_t aAddrBase = smb + (wm * 32 + (lane & 15)) * A_STR + (lane >> 4) * 16;
    const uint32_t bAddrBase = smb + B_OFF + ((lane & 7) + ((lane >> 3) & 1) * 8) * B_STR
                                   + (wn * 64 + (lane >> 4) * 8) * 2;

    int bufi = 0;
    for (int q = 0; q < 18; ++q) {
        if (q < 16) asm volatile("cp.async.wait_group 1;" ::: "memory");
        else        asm volatile("cp.async.wait_group 0;" ::: "memory");
        __syncthreads();
        if (q + 2 < 18) {
            int nb = bufi + 2; if (nb >= 3) nb -= 3;
            conv_load(smb, q + 2, nb, b, tid);
            asm volatile("cp.async.commit_group;" ::: "memory");
        }
        const uint32_t d = bufi * BUFSZ;

        #pragma unroll
        for (int ks = 0; ks < 4; ++ks) {
            uint32_t ah[2][4];
            #pragma unroll
            for (int s = 0; s < 2; ++s) {
                uint32_t addr = aAddrBase + d + (s * 16) * A_STR + ks * 32;
                asm volatile("ldmatrix.sync.aligned.m8n8.x4.shared.b16 {%0,%1,%2,%3}, [%4];"
                             : "=r"(ah[s][0]), "=r"(ah[s][1]), "=r"(ah[s][2]), "=r"(ah[s][3])
                             : "r"(addr));
            }
            #pragma unroll
            for (int i = 0; i < 4; ++i) {
                uint32_t bb[4];
                uint32_t addr = bAddrBase + d + (ks * 16) * B_STR + i * 32;
                asm volatile("ldmatrix.sync.aligned.m8n8.x4.trans.shared.b16 {%0,%1,%2,%3}, [%4];"
                             : "=r"(bb[0]), "=r"(bb[1]), "=r"(bb[2]), "=r"(bb[3])
                             : "r"(addr));
                #pragma unroll
                for (int s = 0; s < 2; ++s) {
                    mma_fp16(acc[s][2 * i],     ah[s], bb[0], bb[1]);
                    mma_fp16(acc[s][2 * i + 1], ah[s], bb[2], bb[3]);
                }
            }
        }
        if (++bufi >= 3) bufi -= 3;
    }
    __syncthreads();    // mainloop done; buffers become epilogue scratch

    // ---------------- fused epilogue ----------------
    float* Rc_s = (float*)smc;                 // [128][260]
    float* Us   = (float*)(smc + 133120);      // [256*19]
    float* Ts   = (float*)(smc + 152576);      // [128][20]
    float* Pm   = Us;                          // partial combine reuse
    float* Ps   = Us + 256;
    float* Pv   = Us + 512;

    const int col_base = wn * 64 + (lane & 3) * 2;
    #pragma unroll
    for (int s = 0; s < 2; ++s) {
        int row = wm * 32 + s * 16 + (lane >> 2);
        #pragma unroll
        for (int j = 0; j < 8; ++j) {
            int col = col_base + j * 8;
            float b0 = __ldg(convb + col), b1 = __ldg(convb + col + 1);
            Rc_s[row * 260 + col]           = tanhf(acc[s][j][0] + b0);
            Rc_s[row * 260 + col + 1]       = tanhf(acc[s][j][1] + b1);
            Rc_s[(row + 8) * 260 + col]     = tanhf(acc[s][j][2] + b0);
            Rc_s[(row + 8) * 260 + col + 1] = tanhf(acc[s][j][3] + b1);
        }
    }
    for (int i = tid; i < 4864; i += 512) Us[i] = U[i];
    __syncthreads();

    // T[l][c] = sum_f Rc_s[l][f] * U[f][c]; warp w -> rows w*8..+7
    #pragma unroll 1
    for (int r = 0; r < 8; ++r) {
        const int l = wid * 8 + r;
        const float* rcl = Rc_s + l * 260;
        float tac[19];
        #pragma unroll
        for (int c = 0; c < 19; ++c) tac[c] = 0.f;
        #pragma unroll
        for (int i = 0; i < 8; ++i) {
            int f = i * 32 + lane;
            float a = rcl[f];
            const float* up = Us + f * 19;
            #pragma unroll
            for (int c = 0; c < 19; ++c) tac[c] += a * up[c];
        }
        #pragma unroll
        for (int c = 0; c < 19; ++c) {
            float v = tac[c];
            #pragma unroll
            for (int o = 16; o; o >>= 1) v += __shfl_xor_sync(0xffffffffu, v, o);
            if (lane == c) Ts[l * 20 + c] = v;
        }
    }
    __syncthreads();

    // head: per-g online softmax over l + maxpool, split across two halves
    const int g = tid & 255;
    const int half = tid >> 8;
    float wl[19];
    #pragma unroll
    for (int c = 0; c < 19; ++c) wl[c] = __ldg(WL + c * 256 + g);

    const int l0 = half * 64;
    float m, S, vmax;
    {
        const float* tl = Ts + l0 * 20;
        float gg = 0.f;
        #pragma unroll
        for (int c = 0; c < 19; ++c) gg += tl[c] * wl[c];
        m = gg; S = 1.f; vmax = Rc_s[l0 * 260 + g];
    }
    for (int l = l0 + 1; l < l0 + 64; ++l) {
        const float* tl = Ts + l * 20;
        float gg = 0.f;
        #pragma unroll
        for (int c = 0; c < 19; ++c) gg += tl[c] * wl[c];
        float rc = Rc_s[l * 260 + g];
        float m2 = fmaxf(m, gg);
        float c1 = __expf(m - m2), c2 = __expf(gg - m2);
        S = S * c1 + c2;
        vmax = fmaxf(vmax * c1, rc * c2);
        m = m2;
    }
    __syncthreads();
    if (half == 1) { Pm[g] = m; Ps[g] = S; Pv[g] = vmax; }
    __syncthreads();
    if (half == 0) {
        float m2 = Pm[g], S2 = Ps[g], v2 = Pv[g];
        float M = fmaxf(m, m2);
        float c1 = __expf(m - M), c2 = __expf(m2 - M);
        float Sc = S * c1 + S2 * c2;
        float V  = fmaxf(vmax * c1, v2 * c2);
        out[(size_t)b * 256 + g] = V / Sc;
    }
}

__global__ void wl_copy_kernel(const float* __restrict__ WL, float* __restrict__ out)
{
    int i = blockIdx.x * 256 + threadIdx.x;
    if (i < 19 * 256) out[512 * 256 + i] = WL[i];
}

// ---------------------------------------------------------------------------
extern "C" void kernel_launch(void* const* d_in, const int* in_sizes, int n_in,
                              void* d_out, int out_size)
{
    const int*   inputs = (const int*)d_in[0];
    const int*   e1s    = (const int*)d_in[1];
    const int*   e1e    = (const int*)d_in[2];
    const int*   e2s    = (const int*)d_in[3];
    const int*   e2e    = (const int*)d_in[4];
    const int*   p1     = (const int*)d_in[5];
    const int*   p2     = (const int*)d_in[6];
    const float* emb    = (const float*)d_in[7];
    const float* pos1   = (const float*)d_in[8];
    const float* pos2   = (const float*)d_in[9];
    const float* convw  = (const float*)d_in[10];
    const float* convb  = (const float*)d_in[11];
    const float* U      = (const float*)d_in[12];
    const float* WL     = (const float*)d_in[13];
    float* out = (float*)d_out;

    const int PREP_SMEM = 13996 * 4;
    cudaFuncSetAttribute(prep_kernel, cudaFuncAttributeMaxDynamicSharedMemorySize, PREP_SMEM);
    cudaFuncSetAttribute(conv_fused_kernel, cudaFuncAttributeMaxDynamicSharedMemorySize, CONV_SMEM);

    prep_kernel<<<512, 256, PREP_SMEM>>>(inputs, e1s, e1e, e2s, e2e, p1, p2, emb, pos1, pos2);
    wsplit_kernel<<<3 * KPAD, 256>>>(convw);
    conv_fused_kernel<<<512, 512, CONV_SMEM>>>(convb, U, WL, out);
    wl_copy_kernel<<<19, 256>>>(WL, out);
}